// round 3
// baseline (speedup 1.0000x reference)
#include <cuda_runtime.h>

// ConvBertLightConv: dynamic depthwise conv, kernel=9, head=64.
// inputs:  [B=8, S=4096, D=768] fp32
// filters: [B, S, H*9=108]      fp32  (softmax over last-9 per head)
// out:     [B, S, H, 64] == [B, S, 768] fp32
//
// HBM-bound (~216 MB). Strategy: shared-tile per (b,h,S-tile) so each input
// element is read from HBM exactly once; register-block 4 output positions
// per thread so shared reads are 3 LDS.128 per output float4 instead of 9.

#define S_LEN   4096
#define D_DIM   768
#define H_NUM   12
#define HD      64
#define KS      9
#define TILE_S  128
#define SREG    4
#define NTHREADS 512          // (TILE_S/SREG) * 16 float4-columns
#define ROWS    (TILE_S + KS - 1)   // 136 staged rows (4-halo each side)

__global__ __launch_bounds__(NTHREADS, 2)
void lightconv_kernel(const float* __restrict__ inputs,
                      const float* __restrict__ filters,
                      float* __restrict__ out)
{
    __shared__ float4 in_s[ROWS * 16];        // 136 rows x 64 floats = 34816 B
    __shared__ float  w_s[TILE_S * KS];       // softmaxed taps, 4608 B

    const int tid = threadIdx.x;
    const int s0  = blockIdx.x * TILE_S;      // tile base position
    const int h   = blockIdx.y;
    const int b   = blockIdx.z;

    // ---- stage input tile (with zero halo) ----
    const float4* in_g =
        (const float4*)(inputs + (size_t)b * S_LEN * D_DIM + h * HD);
    const int row_f4 = D_DIM / 4;             // 192 float4 per full row

    #pragma unroll
    for (int idx = tid; idx < ROWS * 16; idx += NTHREADS) {
        const int r = idx >> 4;               // staged row
        const int c = idx & 15;               // float4 column within head
        const int g = s0 - (KS / 2) + r;      // global sequence position
        float4 v = make_float4(0.f, 0.f, 0.f, 0.f);
        if (g >= 0 && g < S_LEN)
            v = in_g[(size_t)g * row_f4 + c];
        in_s[idx] = v;
    }

    // ---- per-position softmax of the 9 taps ----
    if (tid < TILE_S) {
        const int s = s0 + tid;
        const float* f =
            filters + (size_t)(b * S_LEN + s) * (H_NUM * KS) + h * KS;
        float v[KS];
        float m = -1e30f;
        #pragma unroll
        for (int k = 0; k < KS; k++) { v[k] = f[k]; m = fmaxf(m, v[k]); }
        float sum = 0.f;
        #pragma unroll
        for (int k = 0; k < KS; k++) { v[k] = __expf(v[k] - m); sum += v[k]; }
        const float inv = 1.0f / sum;
        #pragma unroll
        for (int k = 0; k < KS; k++) w_s[tid * KS + k] = v[k] * inv;
    }
    __syncthreads();

    // ---- compute: each thread owns 4 consecutive positions, one f4 column --
    const int c   = tid & 15;                 // float4 column 0..15
    const int sg  = tid >> 4;                 // position group 0..31
    const int sl0 = sg * SREG;                // local base position

    float4 acc[SREG];
    #pragma unroll
    for (int i = 0; i < SREG; i++) acc[i] = make_float4(0.f, 0.f, 0.f, 0.f);

    // staged row (sl0 + j) feeds output i at tap k = j - i
    #pragma unroll
    for (int j = 0; j < SREG + KS - 1; j++) { // 12 shared rows streamed
        const float4 r = in_s[(sl0 + j) * 16 + c];
        #pragma unroll
        for (int i = 0; i < SREG; i++) {
            const int k = j - i;
            if (k >= 0 && k < KS) {
                const float w = w_s[(sl0 + i) * KS + k];
                acc[i].x = fmaf(w, r.x, acc[i].x);
                acc[i].y = fmaf(w, r.y, acc[i].y);
                acc[i].z = fmaf(w, r.z, acc[i].z);
                acc[i].w = fmaf(w, r.w, acc[i].w);
            }
        }
    }

    // ---- store ----
    float4* out_g = (float4*)(out + (size_t)b * S_LEN * D_DIM + h * HD);
    #pragma unroll
    for (int i = 0; i < SREG; i++)
        out_g[(size_t)(s0 + sl0 + i) * row_f4 + c] = acc[i];
}

extern "C" void kernel_launch(void* const* d_in, const int* in_sizes, int n_in,
                              void* d_out, int out_size)
{
    // Disambiguate input order by element counts (inputs=25165824, filters=3538944)
    const float* inputs  = (const float*)d_in[0];
    const float* filters = (const float*)d_in[1];
    if (n_in >= 2 && in_sizes[0] == 8 * 4096 * (H_NUM * KS)) {
        filters = (const float*)d_in[0];
        inputs  = (const float*)d_in[1];
    }
    float* out = (float*)d_out;

    dim3 grid(S_LEN / TILE_S, H_NUM, 8);   // 32 x 12 x 8
    lightconv_kernel<<<grid, NTHREADS>>>(inputs, filters, out);
}

// round 4
// speedup vs baseline: 1.1432x; 1.1432x over previous
#include <cuda_runtime.h>

// ConvBertLightConv: dynamic depthwise conv, kernel=9, head=64.
// inputs:  [B=8, S=4096, D=768] fp32, filters: [B,S,108] fp32, out: [B,S,768] fp32.
//
// HBM-bound (~216 MB floor ≈ 31 us @7TB/s). R3 changes vs R2:
//  - cp.async staging (zfill halo) -> no LDG->reg->STS round trip, fewer regs
//  - filters staged coalesced in their own commit group; softmax overlaps
//    the tile's DRAM latency (wait_group 1 -> softmax -> wait_group 0)
//  - SREG=2 + launch_bounds(512,3): 3 CTAs/SM (occupancy 45% -> ~70%)

#define S_LEN   4096
#define D_DIM   768
#define H_NUM   12
#define HD      64
#define KS      9
#define TILE_S  64
#define SREG    2
#define NTHREADS 512                 // (TILE_S/SREG) * 16 float4-columns
#define ROWS    (TILE_S + KS - 1)    // 72 staged rows (4-halo each side)
#define ROW_F4  (D_DIM / 4)          // 192

__device__ __forceinline__ void cp_async16(void* smem, const void* gmem, int src_bytes) {
    unsigned sa = (unsigned)__cvta_generic_to_shared(smem);
    asm volatile("cp.async.ca.shared.global [%0], [%1], 16, %2;\n"
                 :: "r"(sa), "l"(gmem), "r"(src_bytes));
}
__device__ __forceinline__ void cp_async4(void* smem, const void* gmem) {
    unsigned sa = (unsigned)__cvta_generic_to_shared(smem);
    asm volatile("cp.async.ca.shared.global [%0], [%1], 4;\n"
                 :: "r"(sa), "l"(gmem));
}

__global__ __launch_bounds__(NTHREADS, 3)
void lightconv_kernel(const float* __restrict__ inputs,
                      const float* __restrict__ filters,
                      float* __restrict__ out)
{
    __shared__ float4 in_s[ROWS * 16];        // 72 x 64 floats = 18432 B
    __shared__ float  fraw[TILE_S * KS];      // raw filter taps, 2304 B
    __shared__ float  w_s[TILE_S * KS];       // softmaxed taps, 2304 B

    const int tid = threadIdx.x;
    const int s0  = blockIdx.x * TILE_S;
    const int h   = blockIdx.y;
    const int b   = blockIdx.z;

    // ---- group A: stage raw filters (coalesced contiguous runs) ----
    const float* f_g = filters + (size_t)(b * S_LEN + s0) * (H_NUM * KS) + h * KS;
    #pragma unroll
    for (int idx = tid; idx < TILE_S * KS; idx += NTHREADS) {
        const int r = idx / KS;
        const int k = idx - r * KS;
        cp_async4(&fraw[idx], f_g + (size_t)r * (H_NUM * KS) + k);
    }
    asm volatile("cp.async.commit_group;\n" ::: "memory");

    // ---- group B: stage input tile with zero-filled halo ----
    const float4* in_g = (const float4*)(inputs + (size_t)b * S_LEN * D_DIM + h * HD);
    #pragma unroll
    for (int idx = tid; idx < ROWS * 16; idx += NTHREADS) {
        const int r = idx >> 4;
        const int c = idx & 15;
        const int g = s0 - (KS / 2) + r;
        const int ok = (g >= 0 && g < S_LEN) ? 16 : 0;
        cp_async16(&in_s[idx], &in_g[(size_t)g * ROW_F4 + c], ok);
    }
    asm volatile("cp.async.commit_group;\n" ::: "memory");

    // ---- wait for filters only; softmax overlaps tile DRAM latency ----
    asm volatile("cp.async.wait_group 1;\n" ::: "memory");
    __syncthreads();

    if (tid < TILE_S) {
        float v[KS];
        float m = -1e30f;
        #pragma unroll
        for (int k = 0; k < KS; k++) { v[k] = fraw[tid * KS + k]; m = fmaxf(m, v[k]); }
        float sum = 0.f;
        #pragma unroll
        for (int k = 0; k < KS; k++) { v[k] = __expf(v[k] - m); sum += v[k]; }
        const float inv = 1.0f / sum;
        #pragma unroll
        for (int k = 0; k < KS; k++) w_s[tid * KS + k] = v[k] * inv;
    }

    asm volatile("cp.async.wait_group 0;\n" ::: "memory");
    __syncthreads();

    // ---- compute: each thread owns 2 consecutive positions, one f4 column --
    const int c   = tid & 15;
    const int sl0 = (tid >> 4) * SREG;

    float4 acc[SREG];
    #pragma unroll
    for (int i = 0; i < SREG; i++) acc[i] = make_float4(0.f, 0.f, 0.f, 0.f);

    #pragma unroll
    for (int j = 0; j < SREG + KS - 1; j++) {          // 10 shared rows streamed
        const float4 r = in_s[(sl0 + j) * 16 + c];
        #pragma unroll
        for (int i = 0; i < SREG; i++) {
            const int k = j - i;
            if (k >= 0 && k < KS) {
                const float w = w_s[(sl0 + i) * KS + k];
                acc[i].x = fmaf(w, r.x, acc[i].x);
                acc[i].y = fmaf(w, r.y, acc[i].y);
                acc[i].z = fmaf(w, r.z, acc[i].z);
                acc[i].w = fmaf(w, r.w, acc[i].w);
            }
        }
    }

    float4* out_g = (float4*)(out + (size_t)b * S_LEN * D_DIM + h * HD);
    #pragma unroll
    for (int i = 0; i < SREG; i++)
        out_g[(size_t)(s0 + sl0 + i) * ROW_F4 + c] = acc[i];
}

extern "C" void kernel_launch(void* const* d_in, const int* in_sizes, int n_in,
                              void* d_out, int out_size)
{
    const float* inputs  = (const float*)d_in[0];
    const float* filters = (const float*)d_in[1];
    if (n_in >= 2 && in_sizes[0] == 8 * 4096 * (H_NUM * KS)) {
        filters = (const float*)d_in[0];
        inputs  = (const float*)d_in[1];
    }
    float* out = (float*)d_out;

    dim3 grid(S_LEN / TILE_S, H_NUM, 8);   // 64 x 12 x 8 = 6144 CTAs
    lightconv_kernel<<<grid, NTHREADS>>>(inputs, filters, out);
}

// round 5
// speedup vs baseline: 1.2551x; 1.0978x over previous
#include <cuda_runtime.h>

// ConvBertLightConv: dynamic depthwise conv, kernel=9, head=64.
// inputs:  [B=8, S=4096, D=768] fp32, filters: [B,S,108] fp32, out: [B,S,768].
//
// R4: no smem staging for inputs — direct predicated LDG.128 with 9x reuse
// served by L1 (working set ~19KB/CTA). Removes 1152 LDGSTS + 5120 LDS.128 +
// a barrier per CTA; MLP=12 LDGs/thread keeps DRAM queues full. Filters are
// staged with 3 aligned cp.async16 per row and softmaxed into padded smem.

#define S_LEN   4096
#define D_DIM   768
#define H_NUM   12
#define HD      64
#define KS      9
#define TILE_S  128
#define SREG    4
#define NTHREADS 512                 // (TILE_S/SREG) * 16 float4-columns
#define ROW_F4  (D_DIM / 4)          // 192
#define FP      12                   // padded filter row stride (48B, 16-aligned)

__device__ __forceinline__ void cp_async16(void* smem, const void* gmem) {
    unsigned sa = (unsigned)__cvta_generic_to_shared(smem);
    asm volatile("cp.async.ca.shared.global [%0], [%1], 16;\n"
                 :: "r"(sa), "l"(gmem));
}

__global__ __launch_bounds__(NTHREADS, 3)
void lightconv_kernel(const float* __restrict__ inputs,
                      const float* __restrict__ filters,
                      float* __restrict__ out)
{
    __shared__ float fraw[TILE_S * FP];   // staged raw taps (aligned window)
    __shared__ float w_s [TILE_S * FP];   // softmaxed taps, padded stride 12

    const int tid = threadIdx.x;
    const int s0  = blockIdx.x * TILE_S;
    const int h   = blockIdx.y;
    const int b   = blockIdx.z;

    // ---- stage filters: 3 x 16B aligned cp.async per row ----
    // row bytes are 432 (16-aligned); head offset h*36B aligned down to 16B.
    const int foff  = h * KS;                   // float offset of our 9 taps
    const int a0    = foff & ~3;                // aligned-down float offset
    const int shift = foff & 3;                 // 0..3
    const float* frow0 = filters + (size_t)(b * S_LEN + s0) * (H_NUM * KS) + a0;

    #pragma unroll
    for (int idx = tid; idx < TILE_S * 3; idx += NTHREADS) {
        const int r = idx / 3;
        const int q = idx - r * 3;
        cp_async16(&fraw[r * FP + q * 4], frow0 + (size_t)r * (H_NUM * KS) + q * 4);
    }
    asm volatile("cp.async.commit_group;\n" ::: "memory");
    asm volatile("cp.async.wait_group 0;\n" ::: "memory");
    __syncthreads();

    // ---- per-position softmax of the 9 taps ----
    if (tid < TILE_S) {
        float v[KS];
        float m = -1e30f;
        #pragma unroll
        for (int k = 0; k < KS; k++) {
            v[k] = fraw[tid * FP + shift + k];
            m = fmaxf(m, v[k]);
        }
        float sum = 0.f;
        #pragma unroll
        for (int k = 0; k < KS; k++) { v[k] = __expf(v[k] - m); sum += v[k]; }
        const float inv = 1.0f / sum;
        #pragma unroll
        for (int k = 0; k < KS; k++) w_s[tid * FP + k] = v[k] * inv;
    }
    __syncthreads();

    // ---- compute: thread owns SREG consecutive positions, one f4 column ----
    const int c   = tid & 15;
    const int sl0 = (tid >> 4) * SREG;

    const float4* in_g = (const float4*)(inputs + (size_t)b * S_LEN * D_DIM + h * HD);

    float4 acc[SREG];
    #pragma unroll
    for (int i = 0; i < SREG; i++) acc[i] = make_float4(0.f, 0.f, 0.f, 0.f);

    // input row j feeds output i at tap k = j - i ; global row g = s0+sl0-4+j
    #pragma unroll
    for (int j = 0; j < SREG + KS - 1; j++) {          // 12 rows
        const int g = s0 + sl0 - (KS / 2) + j;
        float4 r = make_float4(0.f, 0.f, 0.f, 0.f);
        if (g >= 0 && g < S_LEN)
            r = __ldg(&in_g[(size_t)g * ROW_F4 + c]);
        #pragma unroll
        for (int i = 0; i < SREG; i++) {
            const int k = j - i;
            if (k >= 0 && k < KS) {
                const float w = w_s[(sl0 + i) * FP + k];
                acc[i].x = fmaf(w, r.x, acc[i].x);
                acc[i].y = fmaf(w, r.y, acc[i].y);
                acc[i].z = fmaf(w, r.z, acc[i].z);
                acc[i].w = fmaf(w, r.w, acc[i].w);
            }
        }
    }

    // ---- store (256B-contiguous per position) ----
    float4* out_g = (float4*)(out + (size_t)b * S_LEN * D_DIM + h * HD);
    #pragma unroll
    for (int i = 0; i < SREG; i++)
        out_g[(size_t)(s0 + sl0 + i) * ROW_F4 + c] = acc[i];
}

extern "C" void kernel_launch(void* const* d_in, const int* in_sizes, int n_in,
                              void* d_out, int out_size)
{
    const float* inputs  = (const float*)d_in[0];
    const float* filters = (const float*)d_in[1];
    if (n_in >= 2 && in_sizes[0] == 8 * 4096 * (H_NUM * KS)) {
        filters = (const float*)d_in[0];
        inputs  = (const float*)d_in[1];
    }
    float* out = (float*)d_out;

    dim3 grid(S_LEN / TILE_S, H_NUM, 8);   // 32 x 12 x 8 = 3072 CTAs
    lightconv_kernel<<<grid, NTHREADS>>>(inputs, filters, out);
}